// round 6
// baseline (speedup 1.0000x reference)
#include <cuda_runtime.h>
#include <cuda_bf16.h>
#include <math.h>

// ---------------- problem constants ----------------
#define BB 64      // batch
#define SS 64      // sentences
#define WW 12      // words per sentence
#define SYM 128
#define HID 256
#define EE 64      // entity size
#define RR 32      // role size
#define VV 32000

typedef unsigned long long u64;

// ---------------- scratch (static device memory; no allocs) ----------------
__device__ __align__(16) float g_sent[BB*SS*SYM];     // 2 MB
__device__ __align__(16) float g_qsum[BB*SYM];
__device__ __align__(16) float g_e1[BB*SS*EE];
__device__ __align__(16) float g_e2[BB*SS*EE];
__device__ __align__(16) float g_r1[BB*SS*RR];
__device__ __align__(16) float g_r2[BB*SS*RR];
__device__ __align__(16) float g_r3[BB*SS*RR];
__device__ __align__(16) float g_qe1[BB*EE];
__device__ __align__(16) float g_qe2[BB*EE];
__device__ __align__(16) float g_qr1[BB*RR];
__device__ __align__(16) float g_qr2[BB*RR];
__device__ __align__(16) float g_qr3[BB*RR];
// TPR permuted: T[b][f][ep][r][c], e = 2*ep + c   (float view; u64 = (e even, e odd) pair)
__device__ __align__(16) float g_T[(size_t)BB*EE*EE*RR];   // 33.5 MB
__device__ __align__(16) float g_raw[3*BB*EE];
__device__ __align__(16) float g_isum[BB*EE];

// ---------------- f32x2 helpers ----------------
__device__ __forceinline__ u64 fma2(u64 a, u64 b, u64 c) {
    u64 d;
    asm("fma.rn.f32x2 %0, %1, %2, %3;" : "=l"(d) : "l"(a), "l"(b), "l"(c));
    return d;
}
__device__ __forceinline__ u64 add2(u64 a, u64 b) {
    u64 d;
    asm("add.rn.f32x2 %0, %1, %2;" : "=l"(d) : "l"(a), "l"(b));
    return d;
}
__device__ __forceinline__ float2 unpack2(u64 a) {
    float2 r;
    asm("mov.b64 {%0,%1}, %2;" : "=f"(r.x), "=f"(r.y) : "l"(a));
    return r;
}
__device__ __forceinline__ u64 pack2(float x, float y) {
    u64 r;
    asm("mov.b64 %0, {%1,%2};" : "=l"(r) : "f"(x), "f"(y));
    return r;
}

// ---------------- 1) embedding ----------------
__global__ void embed_kernel(const int* __restrict__ story, const int* __restrict__ query,
                             const float* __restrict__ WE, const float* __restrict__ PE) {
    int r = blockIdx.x;
    int e = threadIdx.x;   // 128 threads
    const int* idx;
    float* dst;
    if (r < BB*SS) { idx = story + r*WW; dst = g_sent + r*SYM; }
    else           { int rb = r - BB*SS; idx = query + rb*WW; dst = g_qsum + rb*SYM; }
    float acc = 0.f;
#pragma unroll
    for (int w = 0; w < WW; ++w) {
        int t = __ldg(idx + w);
        acc = fmaf(WE[(size_t)t*SYM + e], PE[w*SYM + e], acc);
    }
    dst[e] = acc;
}

// ---------------- 2) fused 5-head MLP (story + query in one grid) ----------------
#define XSTR 132
#define W1S 260
#define W2S64 68
#define W2S32 36
#define HSTR 260
#define WREG 4352
#define MLP_SMEM_FLOATS (32*XSTR + WREG + 32*HSTR)
__global__ void __launch_bounds__(128) mlp5_kernel(
    const float* __restrict__ Xs_story, const float* __restrict__ Xs_query,
    const float* __restrict__ ueW1, const float* __restrict__ ueb1,
    const float* __restrict__ ueW2, const float* __restrict__ ueb2,
    const float* __restrict__ urW1, const float* __restrict__ urb1,
    const float* __restrict__ urW2, const float* __restrict__ urb2,
    const float* __restrict__ ieW1, const float* __restrict__ ieb1,
    const float* __restrict__ ieW2, const float* __restrict__ ieb2,
    const float* __restrict__ irW1, const float* __restrict__ irb1,
    const float* __restrict__ irW2, const float* __restrict__ irb2,
    float* __restrict__ so0, float* __restrict__ so1,
    float* __restrict__ so2, float* __restrict__ so3, float* __restrict__ so4,
    float* __restrict__ qo0, float* __restrict__ qo1,
    float* __restrict__ qo2, float* __restrict__ qo3, float* __restrict__ qo4)
{
    extern __shared__ float smm[];
    float* Xs = smm;                 // 32 x 132
    float* Ws = Xs + 32*XSTR;        // staging region
    float* Hs = Ws + WREG;           // 32 x 260

    int h = blockIdx.y;
    bool is_q = (blockIdx.x >= BB*SS/32);
    const float* X = is_q ? Xs_query : Xs_story;
    int row0 = (is_q ? (blockIdx.x - BB*SS/32) : blockIdx.x) * 32;

    const float *eW1 = is_q ? ieW1 : ueW1, *eb1 = is_q ? ieb1 : ueb1;
    const float *eW2 = is_q ? ieW2 : ueW2, *eb2 = is_q ? ieb2 : ueb2;
    const float *rW1 = is_q ? irW1 : urW1, *rb1 = is_q ? irb1 : urb1;
    const float *rW2 = is_q ? irW2 : urW2, *rb2 = is_q ? irb2 : urb2;

    const float *W1, *b1, *W2, *b2;
    float* out;
    int Dout;
    if (h < 2) {
        W1 = eW1 + (size_t)h*SYM*HID; b1 = eb1 + h*HID;
        W2 = eW2 + (size_t)h*HID*EE;  b2 = eb2 + h*EE;
        out = h ? (is_q ? qo1 : so1) : (is_q ? qo0 : so0); Dout = EE;
    } else {
        int g = h - 2;
        W1 = rW1 + (size_t)g*SYM*HID; b1 = rb1 + g*HID;
        W2 = rW2 + (size_t)g*HID*RR;  b2 = rb2 + g*RR;
        out = (g == 0) ? (is_q ? qo2 : so2)
            : ((g == 1) ? (is_q ? qo3 : so3) : (is_q ? qo4 : so4));
        Dout = RR;
    }

    int tid = threadIdx.x;
    int ty = tid >> 4, tx = tid & 15;   // 8 x 16

    for (int idx = tid; idx < 32*32; idx += 128) {
        int r = idx >> 5, c4 = idx & 31;
        ((float4*)(Xs + r*XSTR))[c4] = ((const float4*)(X + (size_t)(row0 + r)*SYM))[c4];
    }

    // ---- layer 1: [32x128] @ [128x256] + b, tanh ----
    u64 acc2[4][8];
    {
        const u64* bp = (const u64*)(b1 + tx*16);
#pragma unroll
        for (int c = 0; c < 8; ++c) {
            u64 bv = bp[c];
#pragma unroll
            for (int r = 0; r < 4; ++r) acc2[r][c] = bv;
        }
    }
    __syncthreads();

    for (int kk = 0; kk < 8; ++kk) {
        for (int idx = tid; idx < 16*64; idx += 128) {
            int r = idx >> 6, c4 = idx & 63;
            ((float4*)(Ws + r*W1S))[c4] = ((const float4*)(W1 + (size_t)(kk*16 + r)*HID))[c4];
        }
        __syncthreads();
#pragma unroll
        for (int k2 = 0; k2 < 8; ++k2) {
            u64 xx0[4], xx1[4];
#pragma unroll
            for (int r = 0; r < 4; ++r) {
                u64 xu = *(const u64*)(Xs + (ty*4 + r)*XSTR + kk*16 + k2*2);
                float2 xf = unpack2(xu);
                xx0[r] = pack2(xf.x, xf.x);
                xx1[r] = pack2(xf.y, xf.y);
            }
            const ulonglong2* w0p = (const ulonglong2*)(Ws + (k2*2    )*W1S + tx*16);
            const ulonglong2* w1p = (const ulonglong2*)(Ws + (k2*2 + 1)*W1S + tx*16);
#pragma unroll
            for (int q = 0; q < 4; ++q) {
                ulonglong2 w0 = w0p[q];
                ulonglong2 w1 = w1p[q];
#pragma unroll
                for (int r = 0; r < 4; ++r) {
                    acc2[r][2*q  ] = fma2(xx0[r], w0.x, acc2[r][2*q  ]);
                    acc2[r][2*q+1] = fma2(xx0[r], w0.y, acc2[r][2*q+1]);
                    acc2[r][2*q  ] = fma2(xx1[r], w1.x, acc2[r][2*q  ]);
                    acc2[r][2*q+1] = fma2(xx1[r], w1.y, acc2[r][2*q+1]);
                }
            }
        }
        __syncthreads();
    }

#pragma unroll
    for (int r = 0; r < 4; ++r)
#pragma unroll
        for (int c = 0; c < 8; ++c) {
            float2 v = unpack2(acc2[r][c]);
            *(u64*)(Hs + (ty*4 + r)*HSTR + tx*16 + 2*c) = pack2(tanhf(v.x), tanhf(v.y));
        }
    __syncthreads();

    // ---- layer 2: [32x256] @ [256xDout] + b ----
    if (Dout == EE) {
        const int st = W2S64;
        u64 oa[4][2];
        {
            const u64* bp = (const u64*)(b2 + tx*4);
            u64 b0 = bp[0], b1v = bp[1];
#pragma unroll
            for (int r = 0; r < 4; ++r) { oa[r][0] = b0; oa[r][1] = b1v; }
        }
        for (int kk = 0; kk < 4; ++kk) {
            for (int idx = tid; idx < 64*16; idx += 128) {
                int r = idx >> 4, c4 = idx & 15;
                ((float4*)(Ws + r*st))[c4] = ((const float4*)(W2 + (size_t)(kk*64 + r)*EE))[c4];
            }
            __syncthreads();
#pragma unroll
            for (int k2 = 0; k2 < 32; ++k2) {
                u64 hh0[4], hh1[4];
#pragma unroll
                for (int r = 0; r < 4; ++r) {
                    u64 hu = *(const u64*)(Hs + (ty*4 + r)*HSTR + kk*64 + k2*2);
                    float2 hf = unpack2(hu);
                    hh0[r] = pack2(hf.x, hf.x);
                    hh1[r] = pack2(hf.y, hf.y);
                }
                const u64* w0p = (const u64*)(Ws + (k2*2    )*st + tx*4);
                const u64* w1p = (const u64*)(Ws + (k2*2 + 1)*st + tx*4);
                u64 w00 = w0p[0], w01 = w0p[1], w10 = w1p[0], w11 = w1p[1];
#pragma unroll
                for (int r = 0; r < 4; ++r) {
                    oa[r][0] = fma2(hh0[r], w00, oa[r][0]);
                    oa[r][1] = fma2(hh0[r], w01, oa[r][1]);
                    oa[r][0] = fma2(hh1[r], w10, oa[r][0]);
                    oa[r][1] = fma2(hh1[r], w11, oa[r][1]);
                }
            }
            __syncthreads();
        }
#pragma unroll
        for (int r = 0; r < 4; ++r) {
            *(u64*)(out + (size_t)(row0 + ty*4 + r)*EE + tx*4    ) = oa[r][0];
            *(u64*)(out + (size_t)(row0 + ty*4 + r)*EE + tx*4 + 2) = oa[r][1];
        }
    } else {
        const int st = W2S32;
        u64 oa[4];
        {
            u64 b0 = *(const u64*)(b2 + tx*2);
#pragma unroll
            for (int r = 0; r < 4; ++r) oa[r] = b0;
        }
        for (int kk = 0; kk < 4; ++kk) {
            for (int idx = tid; idx < 64*8; idx += 128) {
                int r = idx >> 3, c4 = idx & 7;
                ((float4*)(Ws + r*st))[c4] = ((const float4*)(W2 + (size_t)(kk*64 + r)*RR))[c4];
            }
            __syncthreads();
#pragma unroll
            for (int k2 = 0; k2 < 32; ++k2) {
                u64 hh0[4], hh1[4];
#pragma unroll
                for (int r = 0; r < 4; ++r) {
                    u64 hu = *(const u64*)(Hs + (ty*4 + r)*HSTR + kk*64 + k2*2);
                    float2 hf = unpack2(hu);
                    hh0[r] = pack2(hf.x, hf.x);
                    hh1[r] = pack2(hf.y, hf.y);
                }
                u64 w0 = *(const u64*)(Ws + (k2*2    )*st + tx*2);
                u64 w1 = *(const u64*)(Ws + (k2*2 + 1)*st + tx*2);
#pragma unroll
                for (int r = 0; r < 4; ++r) {
                    oa[r] = fma2(hh0[r], w0, oa[r]);
                    oa[r] = fma2(hh1[r], w1, oa[r]);
                }
            }
            __syncthreads();
        }
#pragma unroll
        for (int r = 0; r < 4; ++r)
            *(u64*)(out + (size_t)(row0 + ty*4 + r)*RR + tx*2) = oa[r];
    }
}

// ---------------- 3) TPR scan: 1 f per warp, 4 CTAs/SM target ----------------
// grid (64, 16), block 128 (4 warps); warp w handles f = by*4 + w; lane = r.
#define SCAN_SMEM_FLOATS (2*SS*EE + 3*SS*RR)
__global__ void __launch_bounds__(128, 4) scan_kernel() {
    extern __shared__ float sm[];
    float* sE1 = sm;                 // 64*64
    float* sE2 = sE1 + SS*EE;
    float* sR1 = sE2 + SS*EE;        // 64*32
    float* sR2 = sR1 + SS*RR;
    float* sR3 = sR2 + SS*RR;

    int b = blockIdx.x;
    int tid = threadIdx.x;
    for (int i = tid; i < SS*EE/4; i += 128) {
        ((float4*)sE1)[i] = ((const float4*)(g_e1 + (size_t)b*SS*EE))[i];
        ((float4*)sE2)[i] = ((const float4*)(g_e2 + (size_t)b*SS*EE))[i];
    }
    for (int i = tid; i < SS*RR/4; i += 128) {
        ((float4*)sR1)[i] = ((const float4*)(g_r1 + (size_t)b*SS*RR))[i];
        ((float4*)sR2)[i] = ((const float4*)(g_r2 + (size_t)b*SS*RR))[i];
        ((float4*)sR3)[i] = ((const float4*)(g_r3 + (size_t)b*SS*RR))[i];
    }
    __syncthreads();

    int warp = tid >> 5, lane = tid & 31;
    int f = blockIdx.y * 4 + warp;

    u64 M[32];
#pragma unroll
    for (int i = 0; i < 32; ++i) M[i] = 0ull;

    for (int s = 0; s < SS; ++s) {
        const ulonglong2* e1q = (const ulonglong2*)(sE1 + s*EE);
        const ulonglong2* e2q = (const ulonglong2*)(sE2 + s*EE);

        // 4-way accumulation chains per dot
        u64 a1A = 0, a1B = 0, a1C = 0, a1D = 0;
        u64 a2A = 0, a2B = 0, a2C = 0, a2D = 0;
#pragma unroll
        for (int i = 0; i < 16; i += 2) {
            ulonglong2 v1 = e1q[i], w1 = e1q[i+1];
            ulonglong2 v2 = e2q[i], w2 = e2q[i+1];
            u64 mA = M[2*i], mB = M[2*i+1], mC = M[2*i+2], mD = M[2*i+3];
            a1A = fma2(v1.x, mA, a1A);  a1B = fma2(v1.y, mB, a1B);
            a1C = fma2(w1.x, mC, a1C);  a1D = fma2(w1.y, mD, a1D);
            a2A = fma2(v2.x, mA, a2A);  a2B = fma2(v2.y, mB, a2B);
            a2C = fma2(w2.x, mC, a2C);  a2D = fma2(w2.y, mD, a2D);
        }
        float2 p1 = unpack2(add2(add2(a1A, a1B), add2(a1C, a1D)));
        float2 p2 = unpack2(add2(add2(a2A, a2B), add2(a2C, a2D)));
        float t1 = p1.x + p1.y;
        float t2 = p2.x + p2.y;

        float r1v = sR1[s*RR + lane];
        float r2v = sR2[s*RR + lane];
        float r3v = sR3[s*RR + lane];

        float u = r1v * t1, v = r2v * t1, w = r3v * t2;
#pragma unroll
        for (int off = 16; off > 0; off >>= 1) {
            u += __shfl_xor_sync(0xffffffffu, u, off);
            v += __shfl_xor_sync(0xffffffffu, v, off);
            w += __shfl_xor_sync(0xffffffffu, w, off);
        }

        float e1f = sE1[s*EE + f];
        float e2f = sE2[s*EE + f];

        float cw = fmaf(r1v, e2f - u, r2v * (u - v));
        float cb = r3v * (e1f - w);
        u64 cw2 = pack2(cw, cw);
        u64 cb2 = pack2(cb, cb);

#pragma unroll
        for (int i = 0; i < 16; ++i) {
            ulonglong2 v1 = e1q[i];
            ulonglong2 v2 = e2q[i];
            M[2*i]   = fma2(v1.x, cw2, fma2(v2.x, cb2, M[2*i]));
            M[2*i+1] = fma2(v1.y, cw2, fma2(v2.y, cb2, M[2*i+1]));
        }
    }

    u64* T = (u64*)g_T;
    size_t base = ((size_t)(b*EE + f)) * 1024;
#pragma unroll
    for (int i = 0; i < 32; ++i)
        T[base + i*32 + lane] = M[i];
}

// ---------------- 4) inference passes ----------------
// grid (BB, 8), block 256; warp w handles f = by*8 + w.
__global__ void __launch_bounds__(256) infer_pass_kernel(int p, const float* __restrict__ qrp,
                                                         const float* __restrict__ ln_g,
                                                         const float* __restrict__ ln_b) {
    __shared__ float cur[64];
    __shared__ float qr[32];
    __shared__ float wv[2048];
    __shared__ float red0[2], red1[2];

    int b = blockIdx.x, tid = threadIdx.x;
    int warp = tid >> 5, lane = tid & 31;

    if (p == 0) {
        if (tid < 64) cur[tid] = g_qe1[b*EE + tid];
    } else {
        float x = 0.f;
        if (tid < 64) {
            x = g_raw[((size_t)(p-1)*BB + b)*EE + tid];
            float s = x;
#pragma unroll
            for (int off = 16; off > 0; off >>= 1) s += __shfl_xor_sync(0xffffffffu, s, off);
            if (lane == 0) red0[warp] = s;
        }
        __syncthreads();
        if (tid < 64) {
            float mean = (red0[0] + red0[1]) * (1.f/64.f);
            float d = x - mean;
            float q = d*d;
#pragma unroll
            for (int off = 16; off > 0; off >>= 1) q += __shfl_xor_sync(0xffffffffu, q, off);
            if (lane == 0) red1[warp] = q;
        }
        __syncthreads();
        if (tid < 64) {
            float mean = (red0[0] + red0[1]) * (1.f/64.f);
            float var  = (red1[0] + red1[1]) * (1.f/64.f);
            cur[tid] = (x - mean) * rsqrtf(var + 1e-5f) * ln_g[(p-1)*EE + tid] + ln_b[(p-1)*EE + tid];
        }
    }
    if (tid >= 224) qr[tid - 224] = qrp[b*RR + (tid - 224)];
    __syncthreads();

    for (int j = tid; j < 2048; j += 256) {
        int e = ((j >> 6) << 1) | (j & 1);
        int r = (j >> 1) & 31;
        wv[j] = cur[e] * qr[r];
    }
    __syncthreads();

    int f = blockIdx.y * 8 + warp;
    const ulonglong2* Tq = (const ulonglong2*)(g_T + ((size_t)(b*EE + f)) * 2048);
    const ulonglong2* wq = (const ulonglong2*)wv;
    u64 accA = 0, accB = 0;
#pragma unroll
    for (int q = 0; q < 16; ++q) {
        ulonglong2 tv = Tq[q*32 + lane];
        ulonglong2 wu = wq[q*32 + lane];
        accA = fma2(tv.x, wu.x, accA);
        accB = fma2(tv.y, wu.y, accB);
    }
    float2 pa = unpack2(accA), pb = unpack2(accB);
    float a = pa.x + pa.y + pb.x + pb.y;
#pragma unroll
    for (int off = 16; off > 0; off >>= 1)
        a += __shfl_xor_sync(0xffffffffu, a, off);
    if (lane == 0) g_raw[((size_t)p*BB + b)*EE + f] = a;
}

// ---------------- 4b) isum = LN(raw0)+LN(raw1)+LN(raw2) ----------------
__global__ void __launch_bounds__(64) isum_kernel(const float* __restrict__ ln_g,
                                                  const float* __restrict__ ln_b) {
    __shared__ float red0[2], red1[2];
    int b = blockIdx.x, tid = threadIdx.x;
    int warp = tid >> 5, lane = tid & 31;
    float s_out = 0.f;
#pragma unroll
    for (int p = 0; p < 3; ++p) {
        float x = g_raw[((size_t)p*BB + b)*EE + tid];
        float s = x;
#pragma unroll
        for (int off = 16; off > 0; off >>= 1) s += __shfl_xor_sync(0xffffffffu, s, off);
        if (lane == 0) red0[warp] = s;
        __syncthreads();
        float mean = (red0[0] + red0[1]) * (1.f/64.f);
        float d = x - mean;
        float q = d*d;
#pragma unroll
        for (int off = 16; off > 0; off >>= 1) q += __shfl_xor_sync(0xffffffffu, q, off);
        if (lane == 0) red1[warp] = q;
        __syncthreads();
        float var = (red1[0] + red1[1]) * (1.f/64.f);
        s_out += (x - mean) * rsqrtf(var + 1e-5f) * ln_g[p*EE + tid] + ln_b[p*EE + tid];
        __syncthreads();
    }
    g_isum[b*EE + tid] = s_out;
}

// ---------------- 5) output GEMM ----------------
__global__ void __launch_bounds__(128) outgemm_kernel(const float* __restrict__ Z,
                                                      float* __restrict__ out) {
    __shared__ float sI[16][64];
    int bx = blockIdx.x, by = blockIdx.y, tid = threadIdx.x;
    for (int idx = tid; idx < 1024; idx += 128)
        sI[idx >> 6][idx & 63] = g_isum[by*1024 + idx];
    __syncthreads();

    int v = bx*128 + tid;
    float acc[16];
#pragma unroll
    for (int i = 0; i < 16; ++i) acc[i] = 0.f;
#pragma unroll 4
    for (int e = 0; e < 64; ++e) {
        float z = __ldg(Z + (size_t)e*VV + v);
#pragma unroll
        for (int i = 0; i < 16; ++i)
            acc[i] = fmaf(sI[i][e], z, acc[i]);
    }
#pragma unroll
    for (int i = 0; i < 16; ++i)
        out[(size_t)(by*16 + i)*VV + v] = acc[i];
}

// ---------------- launch ----------------
extern "C" void kernel_launch(void* const* d_in, const int* in_sizes, int n_in,
                              void* d_out, int out_size) {
    const int*   story = (const int*)d_in[0];
    const int*   query = (const int*)d_in[1];
    const float* WE    = (const float*)d_in[2];
    const float* PE    = (const float*)d_in[3];
    const float* ue_W1 = (const float*)d_in[4];
    const float* ue_b1 = (const float*)d_in[5];
    const float* ue_W2 = (const float*)d_in[6];
    const float* ue_b2 = (const float*)d_in[7];
    const float* ur_W1 = (const float*)d_in[8];
    const float* ur_b1 = (const float*)d_in[9];
    const float* ur_W2 = (const float*)d_in[10];
    const float* ur_b2 = (const float*)d_in[11];
    const float* ie_W1 = (const float*)d_in[12];
    const float* ie_b1 = (const float*)d_in[13];
    const float* ie_W2 = (const float*)d_in[14];
    const float* ie_b2 = (const float*)d_in[15];
    const float* ir_W1 = (const float*)d_in[16];
    const float* ir_b1 = (const float*)d_in[17];
    const float* ir_W2 = (const float*)d_in[18];
    const float* ir_b2 = (const float*)d_in[19];
    const float* ln_g  = (const float*)d_in[20];
    const float* ln_b  = (const float*)d_in[21];
    const float* Z     = (const float*)d_in[22];
    float* out = (float*)d_out;

    const int MLP_SMEM  = MLP_SMEM_FLOATS * (int)sizeof(float);    // ~66 KB
    const int SCAN_SMEM = SCAN_SMEM_FLOATS * (int)sizeof(float);   // 57344 B
    cudaFuncSetAttribute(mlp5_kernel, cudaFuncAttributeMaxDynamicSharedMemorySize, MLP_SMEM);
    cudaFuncSetAttribute(scan_kernel, cudaFuncAttributeMaxDynamicSharedMemorySize, SCAN_SMEM);

    float *d_sent, *d_qsum, *d_e1, *d_e2, *d_r1, *d_r2, *d_r3;
    float *d_qe1, *d_qe2, *d_qr1, *d_qr2, *d_qr3;
    cudaGetSymbolAddress((void**)&d_sent, g_sent);
    cudaGetSymbolAddress((void**)&d_qsum, g_qsum);
    cudaGetSymbolAddress((void**)&d_e1, g_e1);
    cudaGetSymbolAddress((void**)&d_e2, g_e2);
    cudaGetSymbolAddress((void**)&d_r1, g_r1);
    cudaGetSymbolAddress((void**)&d_r2, g_r2);
    cudaGetSymbolAddress((void**)&d_r3, g_r3);
    cudaGetSymbolAddress((void**)&d_qe1, g_qe1);
    cudaGetSymbolAddress((void**)&d_qe2, g_qe2);
    cudaGetSymbolAddress((void**)&d_qr1, g_qr1);
    cudaGetSymbolAddress((void**)&d_qr2, g_qr2);
    cudaGetSymbolAddress((void**)&d_qr3, g_qr3);

    // 1) embeddings
    embed_kernel<<<BB*SS + BB, SYM>>>(story, query, WE, PE);

    // 2) story + query MLPs in one launch
    mlp5_kernel<<<dim3(BB*SS/32 + 2, 5), 128, MLP_SMEM>>>(
        d_sent, d_qsum,
        ue_W1, ue_b1, ue_W2, ue_b2, ur_W1, ur_b1, ur_W2, ur_b2,
        ie_W1, ie_b1, ie_W2, ie_b2, ir_W1, ir_b1, ir_W2, ir_b2,
        d_e1, d_e2, d_r1, d_r2, d_r3,
        d_qe1, d_qe2, d_qr1, d_qr2, d_qr3);

    // 3) TPR scan
    scan_kernel<<<dim3(BB, 16), 128, SCAN_SMEM>>>();

    // 4) inference passes + isum
    infer_pass_kernel<<<dim3(BB, 8), 256>>>(0, d_qr1, ln_g, ln_b);
    infer_pass_kernel<<<dim3(BB, 8), 256>>>(1, d_qr2, ln_g, ln_b);
    infer_pass_kernel<<<dim3(BB, 8), 256>>>(2, d_qr3, ln_g, ln_b);
    isum_kernel<<<BB, 64>>>(ln_g, ln_b);

    // 5) output projection
    outgemm_kernel<<<dim3(VV/128, BB/16), 128>>>(Z, out);
}

// round 7
// speedup vs baseline: 1.5444x; 1.5444x over previous
#include <cuda_runtime.h>
#include <cuda_bf16.h>
#include <math.h>

// ---------------- problem constants ----------------
#define BB 64      // batch
#define SS 64      // sentences
#define WW 12      // words per sentence
#define SYM 128
#define HID 256
#define EE 64      // entity size
#define RR 32      // role size
#define VV 32000

typedef unsigned long long u64;

// ---------------- scratch (static device memory; no allocs) ----------------
__device__ __align__(16) float g_sent[BB*SS*SYM];     // 2 MB
__device__ __align__(16) float g_qsum[BB*SYM];
__device__ __align__(16) float g_e1[BB*SS*EE];
__device__ __align__(16) float g_e2[BB*SS*EE];
__device__ __align__(16) float g_r1[BB*SS*RR];
__device__ __align__(16) float g_r2[BB*SS*RR];
__device__ __align__(16) float g_r3[BB*SS*RR];
__device__ __align__(16) float g_qe1[BB*EE];
__device__ __align__(16) float g_qe2[BB*EE];
__device__ __align__(16) float g_qr1[BB*RR];
__device__ __align__(16) float g_qr2[BB*RR];
__device__ __align__(16) float g_qr3[BB*RR];
// TPR permuted: T[b][f][ep][r][c], e = 2*ep + c   (float view; u64 = (e even, e odd) pair)
__device__ __align__(16) float g_T[(size_t)BB*EE*EE*RR];   // 33.5 MB
__device__ __align__(16) float g_raw[3*BB*EE];
__device__ __align__(16) float g_isum[BB*EE];

// ---------------- f32x2 helpers ----------------
__device__ __forceinline__ u64 fma2(u64 a, u64 b, u64 c) {
    u64 d;
    asm("fma.rn.f32x2 %0, %1, %2, %3;" : "=l"(d) : "l"(a), "l"(b), "l"(c));
    return d;
}
__device__ __forceinline__ u64 add2(u64 a, u64 b) {
    u64 d;
    asm("add.rn.f32x2 %0, %1, %2;" : "=l"(d) : "l"(a), "l"(b));
    return d;
}
__device__ __forceinline__ float2 unpack2(u64 a) {
    float2 r;
    asm("mov.b64 {%0,%1}, %2;" : "=f"(r.x), "=f"(r.y) : "l"(a));
    return r;
}
__device__ __forceinline__ u64 pack2(float x, float y) {
    u64 r;
    asm("mov.b64 %0, {%1,%2};" : "=l"(r) : "f"(x), "f"(y));
    return r;
}

// ---------------- 1) embedding ----------------
__global__ void embed_kernel(const int* __restrict__ story, const int* __restrict__ query,
                             const float* __restrict__ WE, const float* __restrict__ PE) {
    int r = blockIdx.x;
    int e = threadIdx.x;   // 128 threads
    const int* idx;
    float* dst;
    if (r < BB*SS) { idx = story + r*WW; dst = g_sent + r*SYM; }
    else           { int rb = r - BB*SS; idx = query + rb*WW; dst = g_qsum + rb*SYM; }
    float acc = 0.f;
#pragma unroll
    for (int w = 0; w < WW; ++w) {
        int t = __ldg(idx + w);
        acc = fmaf(WE[(size_t)t*SYM + e], PE[w*SYM + e], acc);
    }
    dst[e] = acc;
}

// ---------------- 2) fused 5-head MLP (story + query in one grid) ----------------
#define XSTR 132
#define W1S 260
#define W2S64 68
#define W2S32 36
#define HSTR 260
#define WREG 4352
#define MLP_SMEM_FLOATS (32*XSTR + WREG + 32*HSTR)
__global__ void __launch_bounds__(128) mlp5_kernel(
    const float* __restrict__ Xs_story, const float* __restrict__ Xs_query,
    const float* __restrict__ ueW1, const float* __restrict__ ueb1,
    const float* __restrict__ ueW2, const float* __restrict__ ueb2,
    const float* __restrict__ urW1, const float* __restrict__ urb1,
    const float* __restrict__ urW2, const float* __restrict__ urb2,
    const float* __restrict__ ieW1, const float* __restrict__ ieb1,
    const float* __restrict__ ieW2, const float* __restrict__ ieb2,
    const float* __restrict__ irW1, const float* __restrict__ irb1,
    const float* __restrict__ irW2, const float* __restrict__ irb2,
    float* __restrict__ so0, float* __restrict__ so1,
    float* __restrict__ so2, float* __restrict__ so3, float* __restrict__ so4,
    float* __restrict__ qo0, float* __restrict__ qo1,
    float* __restrict__ qo2, float* __restrict__ qo3, float* __restrict__ qo4)
{
    extern __shared__ float smm[];
    float* Xs = smm;                 // 32 x 132
    float* Ws = Xs + 32*XSTR;        // staging region
    float* Hs = Ws + WREG;           // 32 x 260

    int h = blockIdx.y;
    bool is_q = (blockIdx.x >= BB*SS/32);
    const float* X = is_q ? Xs_query : Xs_story;
    int row0 = (is_q ? (blockIdx.x - BB*SS/32) : blockIdx.x) * 32;

    const float *eW1 = is_q ? ieW1 : ueW1, *eb1 = is_q ? ieb1 : ueb1;
    const float *eW2 = is_q ? ieW2 : ueW2, *eb2 = is_q ? ieb2 : ueb2;
    const float *rW1 = is_q ? irW1 : urW1, *rb1 = is_q ? irb1 : urb1;
    const float *rW2 = is_q ? irW2 : urW2, *rb2 = is_q ? irb2 : urb2;

    const float *W1, *b1, *W2, *b2;
    float* out;
    int Dout;
    if (h < 2) {
        W1 = eW1 + (size_t)h*SYM*HID; b1 = eb1 + h*HID;
        W2 = eW2 + (size_t)h*HID*EE;  b2 = eb2 + h*EE;
        out = h ? (is_q ? qo1 : so1) : (is_q ? qo0 : so0); Dout = EE;
    } else {
        int g = h - 2;
        W1 = rW1 + (size_t)g*SYM*HID; b1 = rb1 + g*HID;
        W2 = rW2 + (size_t)g*HID*RR;  b2 = rb2 + g*RR;
        out = (g == 0) ? (is_q ? qo2 : so2)
            : ((g == 1) ? (is_q ? qo3 : so3) : (is_q ? qo4 : so4));
        Dout = RR;
    }

    int tid = threadIdx.x;
    int ty = tid >> 4, tx = tid & 15;   // 8 x 16

    for (int idx = tid; idx < 32*32; idx += 128) {
        int r = idx >> 5, c4 = idx & 31;
        ((float4*)(Xs + r*XSTR))[c4] = ((const float4*)(X + (size_t)(row0 + r)*SYM))[c4];
    }

    // ---- layer 1: [32x128] @ [128x256] + b, tanh ----
    u64 acc2[4][8];
    {
        const u64* bp = (const u64*)(b1 + tx*16);
#pragma unroll
        for (int c = 0; c < 8; ++c) {
            u64 bv = bp[c];
#pragma unroll
            for (int r = 0; r < 4; ++r) acc2[r][c] = bv;
        }
    }
    __syncthreads();

    for (int kk = 0; kk < 8; ++kk) {
        for (int idx = tid; idx < 16*64; idx += 128) {
            int r = idx >> 6, c4 = idx & 63;
            ((float4*)(Ws + r*W1S))[c4] = ((const float4*)(W1 + (size_t)(kk*16 + r)*HID))[c4];
        }
        __syncthreads();
#pragma unroll
        for (int k2 = 0; k2 < 8; ++k2) {
            u64 xx0[4], xx1[4];
#pragma unroll
            for (int r = 0; r < 4; ++r) {
                u64 xu = *(const u64*)(Xs + (ty*4 + r)*XSTR + kk*16 + k2*2);
                float2 xf = unpack2(xu);
                xx0[r] = pack2(xf.x, xf.x);
                xx1[r] = pack2(xf.y, xf.y);
            }
            const ulonglong2* w0p = (const ulonglong2*)(Ws + (k2*2    )*W1S + tx*16);
            const ulonglong2* w1p = (const ulonglong2*)(Ws + (k2*2 + 1)*W1S + tx*16);
#pragma unroll
            for (int q = 0; q < 4; ++q) {
                ulonglong2 w0 = w0p[q];
                ulonglong2 w1 = w1p[q];
#pragma unroll
                for (int r = 0; r < 4; ++r) {
                    acc2[r][2*q  ] = fma2(xx0[r], w0.x, acc2[r][2*q  ]);
                    acc2[r][2*q+1] = fma2(xx0[r], w0.y, acc2[r][2*q+1]);
                    acc2[r][2*q  ] = fma2(xx1[r], w1.x, acc2[r][2*q  ]);
                    acc2[r][2*q+1] = fma2(xx1[r], w1.y, acc2[r][2*q+1]);
                }
            }
        }
        __syncthreads();
    }

#pragma unroll
    for (int r = 0; r < 4; ++r)
#pragma unroll
        for (int c = 0; c < 8; ++c) {
            float2 v = unpack2(acc2[r][c]);
            *(u64*)(Hs + (ty*4 + r)*HSTR + tx*16 + 2*c) = pack2(tanhf(v.x), tanhf(v.y));
        }
    __syncthreads();

    // ---- layer 2: [32x256] @ [256xDout] + b ----
    if (Dout == EE) {
        const int st = W2S64;
        u64 oa[4][2];
        {
            const u64* bp = (const u64*)(b2 + tx*4);
            u64 b0 = bp[0], b1v = bp[1];
#pragma unroll
            for (int r = 0; r < 4; ++r) { oa[r][0] = b0; oa[r][1] = b1v; }
        }
        for (int kk = 0; kk < 4; ++kk) {
            for (int idx = tid; idx < 64*16; idx += 128) {
                int r = idx >> 4, c4 = idx & 15;
                ((float4*)(Ws + r*st))[c4] = ((const float4*)(W2 + (size_t)(kk*64 + r)*EE))[c4];
            }
            __syncthreads();
#pragma unroll
            for (int k2 = 0; k2 < 32; ++k2) {
                u64 hh0[4], hh1[4];
#pragma unroll
                for (int r = 0; r < 4; ++r) {
                    u64 hu = *(const u64*)(Hs + (ty*4 + r)*HSTR + kk*64 + k2*2);
                    float2 hf = unpack2(hu);
                    hh0[r] = pack2(hf.x, hf.x);
                    hh1[r] = pack2(hf.y, hf.y);
                }
                const u64* w0p = (const u64*)(Ws + (k2*2    )*st + tx*4);
                const u64* w1p = (const u64*)(Ws + (k2*2 + 1)*st + tx*4);
                u64 w00 = w0p[0], w01 = w0p[1], w10 = w1p[0], w11 = w1p[1];
#pragma unroll
                for (int r = 0; r < 4; ++r) {
                    oa[r][0] = fma2(hh0[r], w00, oa[r][0]);
                    oa[r][1] = fma2(hh0[r], w01, oa[r][1]);
                    oa[r][0] = fma2(hh1[r], w10, oa[r][0]);
                    oa[r][1] = fma2(hh1[r], w11, oa[r][1]);
                }
            }
            __syncthreads();
        }
#pragma unroll
        for (int r = 0; r < 4; ++r) {
            *(u64*)(out + (size_t)(row0 + ty*4 + r)*EE + tx*4    ) = oa[r][0];
            *(u64*)(out + (size_t)(row0 + ty*4 + r)*EE + tx*4 + 2) = oa[r][1];
        }
    } else {
        const int st = W2S32;
        u64 oa[4];
        {
            u64 b0 = *(const u64*)(b2 + tx*2);
#pragma unroll
            for (int r = 0; r < 4; ++r) oa[r] = b0;
        }
        for (int kk = 0; kk < 4; ++kk) {
            for (int idx = tid; idx < 64*8; idx += 128) {
                int r = idx >> 3, c4 = idx & 7;
                ((float4*)(Ws + r*st))[c4] = ((const float4*)(W2 + (size_t)(kk*64 + r)*RR))[c4];
            }
            __syncthreads();
#pragma unroll
            for (int k2 = 0; k2 < 32; ++k2) {
                u64 hh0[4], hh1[4];
#pragma unroll
                for (int r = 0; r < 4; ++r) {
                    u64 hu = *(const u64*)(Hs + (ty*4 + r)*HSTR + kk*64 + k2*2);
                    float2 hf = unpack2(hu);
                    hh0[r] = pack2(hf.x, hf.x);
                    hh1[r] = pack2(hf.y, hf.y);
                }
                u64 w0 = *(const u64*)(Ws + (k2*2    )*st + tx*2);
                u64 w1 = *(const u64*)(Ws + (k2*2 + 1)*st + tx*2);
#pragma unroll
                for (int r = 0; r < 4; ++r) {
                    oa[r] = fma2(hh0[r], w0, oa[r]);
                    oa[r] = fma2(hh1[r], w1, oa[r]);
                }
            }
            __syncthreads();
        }
#pragma unroll
        for (int r = 0; r < 4; ++r)
            *(u64*)(out + (size_t)(row0 + ty*4 + r)*RR + tx*2) = oa[r];
    }
}

// ---------------- 3) TPR scan: 1 f per warp, 3 CTAs/SM (R4-proven config) ----------------
// grid (64, 16), block 128 (4 warps); warp w handles f = by*4 + w; lane = r.
#define SCAN_SMEM_FLOATS (2*SS*EE + 3*SS*RR)
__global__ void __launch_bounds__(128, 3) scan_kernel() {
    extern __shared__ float sm[];
    float* sE1 = sm;                 // 64*64
    float* sE2 = sE1 + SS*EE;
    float* sR1 = sE2 + SS*EE;        // 64*32
    float* sR2 = sR1 + SS*RR;
    float* sR3 = sR2 + SS*RR;

    int b = blockIdx.x;
    int tid = threadIdx.x;
    for (int i = tid; i < SS*EE/4; i += 128) {
        ((float4*)sE1)[i] = ((const float4*)(g_e1 + (size_t)b*SS*EE))[i];
        ((float4*)sE2)[i] = ((const float4*)(g_e2 + (size_t)b*SS*EE))[i];
    }
    for (int i = tid; i < SS*RR/4; i += 128) {
        ((float4*)sR1)[i] = ((const float4*)(g_r1 + (size_t)b*SS*RR))[i];
        ((float4*)sR2)[i] = ((const float4*)(g_r2 + (size_t)b*SS*RR))[i];
        ((float4*)sR3)[i] = ((const float4*)(g_r3 + (size_t)b*SS*RR))[i];
    }
    __syncthreads();

    int warp = tid >> 5, lane = tid & 31;
    int f = blockIdx.y * 4 + warp;

    u64 M[32];
#pragma unroll
    for (int i = 0; i < 32; ++i) M[i] = 0ull;

    for (int s = 0; s < SS; ++s) {
        const ulonglong2* e1q = (const ulonglong2*)(sE1 + s*EE);
        const ulonglong2* e2q = (const ulonglong2*)(sE2 + s*EE);

        // 4-way accumulation chains per dot
        u64 a1A = 0, a1B = 0, a1C = 0, a1D = 0;
        u64 a2A = 0, a2B = 0, a2C = 0, a2D = 0;
#pragma unroll
        for (int i = 0; i < 16; i += 2) {
            ulonglong2 v1 = e1q[i], w1 = e1q[i+1];
            ulonglong2 v2 = e2q[i], w2 = e2q[i+1];
            u64 mA = M[2*i], mB = M[2*i+1], mC = M[2*i+2], mD = M[2*i+3];
            a1A = fma2(v1.x, mA, a1A);  a1B = fma2(v1.y, mB, a1B);
            a1C = fma2(w1.x, mC, a1C);  a1D = fma2(w1.y, mD, a1D);
            a2A = fma2(v2.x, mA, a2A);  a2B = fma2(v2.y, mB, a2B);
            a2C = fma2(w2.x, mC, a2C);  a2D = fma2(w2.y, mD, a2D);
        }
        float2 p1 = unpack2(add2(add2(a1A, a1B), add2(a1C, a1D)));
        float2 p2 = unpack2(add2(add2(a2A, a2B), add2(a2C, a2D)));
        float t1 = p1.x + p1.y;
        float t2 = p2.x + p2.y;

        float r1v = sR1[s*RR + lane];
        float r2v = sR2[s*RR + lane];
        float r3v = sR3[s*RR + lane];

        float u = r1v * t1, v = r2v * t1, w = r3v * t2;
#pragma unroll
        for (int off = 16; off > 0; off >>= 1) {
            u += __shfl_xor_sync(0xffffffffu, u, off);
            v += __shfl_xor_sync(0xffffffffu, v, off);
            w += __shfl_xor_sync(0xffffffffu, w, off);
        }

        float e1f = sE1[s*EE + f];
        float e2f = sE2[s*EE + f];

        float cw = fmaf(r1v, e2f - u, r2v * (u - v));
        float cb = r3v * (e1f - w);
        u64 cw2 = pack2(cw, cw);
        u64 cb2 = pack2(cb, cb);

#pragma unroll
        for (int i = 0; i < 16; ++i) {
            ulonglong2 v1 = e1q[i];
            ulonglong2 v2 = e2q[i];
            M[2*i]   = fma2(v1.x, cw2, fma2(v2.x, cb2, M[2*i]));
            M[2*i+1] = fma2(v1.y, cw2, fma2(v2.y, cb2, M[2*i+1]));
        }
    }

    u64* T = (u64*)g_T;
    size_t base = ((size_t)(b*EE + f)) * 1024;
#pragma unroll
    for (int i = 0; i < 32; ++i)
        T[base + i*32 + lane] = M[i];
}

// ---------------- 4) inference passes ----------------
// grid (BB, 8), block 256; warp w handles f = by*8 + w.
__global__ void __launch_bounds__(256) infer_pass_kernel(int p, const float* __restrict__ qrp,
                                                         const float* __restrict__ ln_g,
                                                         const float* __restrict__ ln_b) {
    __shared__ float cur[64];
    __shared__ float qr[32];
    __shared__ float wv[2048];
    __shared__ float red0[2], red1[2];

    int b = blockIdx.x, tid = threadIdx.x;
    int warp = tid >> 5, lane = tid & 31;

    if (p == 0) {
        if (tid < 64) cur[tid] = g_qe1[b*EE + tid];
    } else {
        float x = 0.f;
        if (tid < 64) {
            x = g_raw[((size_t)(p-1)*BB + b)*EE + tid];
            float s = x;
#pragma unroll
            for (int off = 16; off > 0; off >>= 1) s += __shfl_xor_sync(0xffffffffu, s, off);
            if (lane == 0) red0[warp] = s;
        }
        __syncthreads();
        if (tid < 64) {
            float mean = (red0[0] + red0[1]) * (1.f/64.f);
            float d = x - mean;
            float q = d*d;
#pragma unroll
            for (int off = 16; off > 0; off >>= 1) q += __shfl_xor_sync(0xffffffffu, q, off);
            if (lane == 0) red1[warp] = q;
        }
        __syncthreads();
        if (tid < 64) {
            float mean = (red0[0] + red0[1]) * (1.f/64.f);
            float var  = (red1[0] + red1[1]) * (1.f/64.f);
            cur[tid] = (x - mean) * rsqrtf(var + 1e-5f) * ln_g[(p-1)*EE + tid] + ln_b[(p-1)*EE + tid];
        }
    }
    if (tid >= 224) qr[tid - 224] = qrp[b*RR + (tid - 224)];
    __syncthreads();

    for (int j = tid; j < 2048; j += 256) {
        int e = ((j >> 6) << 1) | (j & 1);
        int r = (j >> 1) & 31;
        wv[j] = cur[e] * qr[r];
    }
    __syncthreads();

    int f = blockIdx.y * 8 + warp;
    const ulonglong2* Tq = (const ulonglong2*)(g_T + ((size_t)(b*EE + f)) * 2048);
    const ulonglong2* wq = (const ulonglong2*)wv;
    u64 accA = 0, accB = 0;
#pragma unroll
    for (int q = 0; q < 16; ++q) {
        ulonglong2 tv = Tq[q*32 + lane];
        ulonglong2 wu = wq[q*32 + lane];
        accA = fma2(tv.x, wu.x, accA);
        accB = fma2(tv.y, wu.y, accB);
    }
    float2 pa = unpack2(accA), pb = unpack2(accB);
    float a = pa.x + pa.y + pb.x + pb.y;
#pragma unroll
    for (int off = 16; off > 0; off >>= 1)
        a += __shfl_xor_sync(0xffffffffu, a, off);
    if (lane == 0) g_raw[((size_t)p*BB + b)*EE + f] = a;
}

// ---------------- 4b) isum = LN(raw0)+LN(raw1)+LN(raw2) ----------------
__global__ void __launch_bounds__(64) isum_kernel(const float* __restrict__ ln_g,
                                                  const float* __restrict__ ln_b) {
    __shared__ float red0[2], red1[2];
    int b = blockIdx.x, tid = threadIdx.x;
    int warp = tid >> 5, lane = tid & 31;
    float s_out = 0.f;
#pragma unroll
    for (int p = 0; p < 3; ++p) {
        float x = g_raw[((size_t)p*BB + b)*EE + tid];
        float s = x;
#pragma unroll
        for (int off = 16; off > 0; off >>= 1) s += __shfl_xor_sync(0xffffffffu, s, off);
        if (lane == 0) red0[warp] = s;
        __syncthreads();
        float mean = (red0[0] + red0[1]) * (1.f/64.f);
        float d = x - mean;
        float q = d*d;
#pragma unroll
        for (int off = 16; off > 0; off >>= 1) q += __shfl_xor_sync(0xffffffffu, q, off);
        if (lane == 0) red1[warp] = q;
        __syncthreads();
        float var = (red1[0] + red1[1]) * (1.f/64.f);
        s_out += (x - mean) * rsqrtf(var + 1e-5f) * ln_g[p*EE + tid] + ln_b[p*EE + tid];
        __syncthreads();
    }
    g_isum[b*EE + tid] = s_out;
}

// ---------------- 5) output GEMM ----------------
__global__ void __launch_bounds__(128) outgemm_kernel(const float* __restrict__ Z,
                                                      float* __restrict__ out) {
    __shared__ float sI[16][64];
    int bx = blockIdx.x, by = blockIdx.y, tid = threadIdx.x;
    for (int idx = tid; idx < 1024; idx += 128)
        sI[idx >> 6][idx & 63] = g_isum[by*1024 + idx];
    __syncthreads();

    int v = bx*128 + tid;
    float acc[16];
#pragma unroll
    for (int i = 0; i < 16; ++i) acc[i] = 0.f;
#pragma unroll 4
    for (int e = 0; e < 64; ++e) {
        float z = __ldg(Z + (size_t)e*VV + v);
#pragma unroll
        for (int i = 0; i < 16; ++i)
            acc[i] = fmaf(sI[i][e], z, acc[i]);
    }
#pragma unroll
    for (int i = 0; i < 16; ++i)
        out[(size_t)(by*16 + i)*VV + v] = acc[i];
}

// ---------------- launch ----------------
extern "C" void kernel_launch(void* const* d_in, const int* in_sizes, int n_in,
                              void* d_out, int out_size) {
    const int*   story = (const int*)d_in[0];
    const int*   query = (const int*)d_in[1];
    const float* WE    = (const float*)d_in[2];
    const float* PE    = (const float*)d_in[3];
    const float* ue_W1 = (const float*)d_in[4];
    const float* ue_b1 = (const float*)d_in[5];
    const float* ue_W2 = (const float*)d_in[6];
    const float* ue_b2 = (const float*)d_in[7];
    const float* ur_W1 = (const float*)d_in[8];
    const float* ur_b1 = (const float*)d_in[9];
    const float* ur_W2 = (const float*)d_in[10];
    const float* ur_b2 = (const float*)d_in[11];
    const float* ie_W1 = (const float*)d_in[12];
    const float* ie_b1 = (const float*)d_in[13];
    const float* ie_W2 = (const float*)d_in[14];
    const float* ie_b2 = (const float*)d_in[15];
    const float* ir_W1 = (const float*)d_in[16];
    const float* ir_b1 = (const float*)d_in[17];
    const float* ir_W2 = (const float*)d_in[18];
    const float* ir_b2 = (const float*)d_in[19];
    const float* ln_g  = (const float*)d_in[20];
    const float* ln_b  = (const float*)d_in[21];
    const float* Z     = (const float*)d_in[22];
    float* out = (float*)d_out;

    const int MLP_SMEM  = MLP_SMEM_FLOATS * (int)sizeof(float);    // ~66 KB
    const int SCAN_SMEM = SCAN_SMEM_FLOATS * (int)sizeof(float);   // 57344 B
    cudaFuncSetAttribute(mlp5_kernel, cudaFuncAttributeMaxDynamicSharedMemorySize, MLP_SMEM);
    cudaFuncSetAttribute(scan_kernel, cudaFuncAttributeMaxDynamicSharedMemorySize, SCAN_SMEM);

    float *d_sent, *d_qsum, *d_e1, *d_e2, *d_r1, *d_r2, *d_r3;
    float *d_qe1, *d_qe2, *d_qr1, *d_qr2, *d_qr3;
    cudaGetSymbolAddress((void**)&d_sent, g_sent);
    cudaGetSymbolAddress((void**)&d_qsum, g_qsum);
    cudaGetSymbolAddress((void**)&d_e1, g_e1);
    cudaGetSymbolAddress((void**)&d_e2, g_e2);
    cudaGetSymbolAddress((void**)&d_r1, g_r1);
    cudaGetSymbolAddress((void**)&d_r2, g_r2);
    cudaGetSymbolAddress((void**)&d_r3, g_r3);
    cudaGetSymbolAddress((void**)&d_qe1, g_qe1);
    cudaGetSymbolAddress((void**)&d_qe2, g_qe2);
    cudaGetSymbolAddress((void**)&d_qr1, g_qr1);
    cudaGetSymbolAddress((void**)&d_qr2, g_qr2);
    cudaGetSymbolAddress((void**)&d_qr3, g_qr3);

    // 1) embeddings
    embed_kernel<<<BB*SS + BB, SYM>>>(story, query, WE, PE);

    // 2) story + query MLPs in one launch
    mlp5_kernel<<<dim3(BB*SS/32 + 2, 5), 128, MLP_SMEM>>>(
        d_sent, d_qsum,
        ue_W1, ue_b1, ue_W2, ue_b2, ur_W1, ur_b1, ur_W2, ur_b2,
        ie_W1, ie_b1, ie_W2, ie_b2, ir_W1, ir_b1, ir_W2, ir_b2,
        d_e1, d_e2, d_r1, d_r2, d_r3,
        d_qe1, d_qe2, d_qr1, d_qr2, d_qr3);

    // 3) TPR scan
    scan_kernel<<<dim3(BB, 16), 128, SCAN_SMEM>>>();

    // 4) inference passes + isum
    infer_pass_kernel<<<dim3(BB, 8), 256>>>(0, d_qr1, ln_g, ln_b);
    infer_pass_kernel<<<dim3(BB, 8), 256>>>(1, d_qr2, ln_g, ln_b);
    infer_pass_kernel<<<dim3(BB, 8), 256>>>(2, d_qr3, ln_g, ln_b);
    isum_kernel<<<BB, 64>>>(ln_g, ln_b);

    // 5) output projection
    outgemm_kernel<<<dim3(VV/128, BB/16), 128>>>(Z, out);
}